// round 5
// baseline (speedup 1.0000x reference)
#include <cuda_runtime.h>
#include <cuda_bf16.h>
#include <cstdint>

// Problem constants
#define BATCH 16
#define CH    128
#define HH    64
#define WW    64
#define HW    4096          // 64*64
#define CQ    16            // C/8
#define CV    64            // C/2
#define TT    1024          // HW/4 pooled positions
#define NEG_INF (-3.402823466e38f)

typedef unsigned long long ull;

// ---------------- scratch (static device memory; no allocs allowed) ----------------
__device__ float g_Wt[CQ * CH];     // normalized theta weight  [16,128]
__device__ float g_Wp[CQ * CH];     // normalized phi weight    [16,128]
__device__ float g_Wg[CV * CH];     // normalized g weight      [64,128]
__device__ float g_Wo[CH * CV];     // normalized o weight      [128,64]

__device__ float d_theta[BATCH * HW * CQ];   // [b][s][16]
__device__ float d_phi[BATCH * TT * CQ];     // [b][t][16]
__device__ float d_g[BATCH * TT * CV];       // [b][t][64]
__device__ float d_o[BATCH * HW * CV];       // [b][s][64]

// ---------------- packed f32x2 helpers (sm_103a) ----------------
__device__ __forceinline__ ull pack2(float v) {
    ull r;
    unsigned int u = __float_as_uint(v);
    asm("mov.b64 %0, {%1, %1};" : "=l"(r) : "r"(u));
    return r;
}
__device__ __forceinline__ void fma2(ull& d, ull a, ull b) {
    asm("fma.rn.f32x2 %0, %1, %2, %0;" : "+l"(d) : "l"(a), "l"(b));
}
__device__ __forceinline__ float2 unpack2(ull v) {
    float2 r;
    r.x = __uint_as_float((unsigned int)(v & 0xffffffffull));
    r.y = __uint_as_float((unsigned int)(v >> 32));
    return r;
}

__device__ __forceinline__ unsigned to_tf32(float f) {
    unsigned r;
    asm("cvt.rna.tf32.f32 %0, %1;" : "=r"(r) : "f"(f));
    return r;
}

// mma.sync m16n8k8 tf32, C += A*B
__device__ __forceinline__ void mma8(float c[4], const unsigned a[4],
                                     unsigned b0, unsigned b1) {
    asm("mma.sync.aligned.m16n8k8.row.col.f32.tf32.tf32.f32 "
        "{%0,%1,%2,%3}, {%4,%5,%6,%7}, {%8,%9}, {%0,%1,%2,%3};"
        : "+f"(c[0]), "+f"(c[1]), "+f"(c[2]), "+f"(c[3])
        : "r"(a[0]), "r"(a[1]), "r"(a[2]), "r"(a[3]), "r"(b0), "r"(b1));
}

// cp.async helpers
__device__ __forceinline__ void cp16(unsigned dst, const void* src) {
    asm volatile("cp.async.ca.shared.global [%0], [%1], 16;" :: "r"(dst), "l"(src));
}
__device__ __forceinline__ void cp_commit() {
    asm volatile("cp.async.commit_group;");
}
__device__ __forceinline__ void cp_wait0() {
    asm volatile("cp.async.wait_group 0;" ::: "memory");
}

// ---------------- spectral norm ----------------
__device__ __forceinline__ float block_reduce_sum_128(float v, float* sred) {
    int t = threadIdx.x;
    sred[t] = v;
    __syncthreads();
    #pragma unroll
    for (int s = 64; s > 0; s >>= 1) {
        if (t < s) sred[t] += sred[t + s];
        __syncthreads();
    }
    float r = sred[0];
    __syncthreads();
    return r;
}

__global__ void sn_kernel(const float* w_theta, const float* w_phi,
                          const float* w_g, const float* w_o,
                          const float* u_theta, const float* u_phi,
                          const float* u_g, const float* u_o) {
    __shared__ float sv[128];
    __shared__ float sred[128];
    const float* W; const float* u; float* Wn; int O, I;
    switch (blockIdx.x) {
        case 0:  W = w_theta; u = u_theta; Wn = g_Wt; O = CQ; I = CH; break;
        case 1:  W = w_phi;   u = u_phi;   Wn = g_Wp; O = CQ; I = CH; break;
        case 2:  W = w_g;     u = u_g;     Wn = g_Wg; O = CV; I = CH; break;
        default: W = w_o;     u = u_o;     Wn = g_Wo; O = CH; I = CV; break;
    }
    int t = threadIdx.x;
    float vr = 0.f;
    if (t < I) {
        for (int o = 0; o < O; o++) vr += u[o] * W[o * I + t];
    }
    float nv2 = block_reduce_sum_128((t < I) ? vr * vr : 0.f, sred);
    float inv = 1.f / fmaxf(sqrtf(nv2), 1e-12f);
    if (t < I) sv[t] = vr * inv;
    __syncthreads();
    float ur = 0.f;
    if (t < O) {
        for (int i = 0; i < I; i++) ur += sv[i] * W[t * I + i];
    }
    float nu2 = block_reduce_sum_128((t < O) ? ur * ur : 0.f, sred);
    float invu = 1.f / fmaxf(sqrtf(nu2), 1e-12f);
    float sigma = block_reduce_sum_128((t < O) ? ur * ur * invu : 0.f, sred);
    float wscale = 1.f / sigma;
    for (int k = t; k < O * I; k += 128) Wn[k] = W[k] * wscale;
}

// ---------------- theta conv: [16 out] per pixel, layout [b][s][16] ----------------
__global__ __launch_bounds__(256) void theta_kernel(const float* __restrict__ x) {
    __shared__ float sW[CH * CQ];   // transposed [c][o]
    for (int i = threadIdx.x; i < CH * CQ; i += 256) {
        int c = i >> 4, o = i & 15;
        sW[i] = g_Wt[o * CH + c];
    }
    __syncthreads();
    int p = blockIdx.x * 256 + threadIdx.x;          // 0..65535
    int b = p >> 12, s = p & 4095;
    const float* xp = x + (size_t)b * CH * HW + s;
    ull acc[8];
    #pragma unroll
    for (int j = 0; j < 8; j++) acc[j] = 0ull;
    #pragma unroll 8
    for (int c = 0; c < CH; c++) {
        ull X = pack2(xp[c * HW]);
        const float* wr = &sW[c * CQ];
        #pragma unroll
        for (int j = 0; j < 4; j++) {
            ulonglong2 w = *(const ulonglong2*)(wr + j * 4);
            fma2(acc[2*j],     w.x, X);
            fma2(acc[2*j + 1], w.y, X);
        }
    }
    float4* outp = (float4*)&d_theta[(size_t)p * CQ];
    #pragma unroll
    for (int j = 0; j < 4; j++) {
        float2 a0 = unpack2(acc[2*j]);
        float2 a1 = unpack2(acc[2*j + 1]);
        outp[j] = make_float4(a0.x, a0.y, a1.x, a1.y);
    }
}

// ---------------- pooled convs: 1 thread per (pooled pos, subpixel) ----------------
template <int NOUT, int WSEL>
__global__ __launch_bounds__(128) void poolconv_kernel(const float* __restrict__ x) {
    __shared__ float sW[CH * NOUT];  // transposed [c][o]
    int ochOff = blockIdx.y * NOUT;
    const float* Wsrc = (WSEL == 0 ? g_Wp : g_Wg);
    for (int i = threadIdx.x; i < CH * NOUT; i += 128) {
        int c = i / NOUT, o = i % NOUT;
        sW[i] = Wsrc[(ochOff + o) * CH + c];
    }
    __syncthreads();
    int tid = blockIdx.x * 128 + threadIdx.x;   // 0..65535
    int pooled = tid >> 2, sub = tid & 3;       // pooled pos, subpixel
    int b = pooled >> 10, t = pooled & 1023;
    int hp = t >> 5, wp = t & 31;
    int pix = (2 * hp + (sub >> 1)) * WW + 2 * wp + (sub & 1);
    const float* xp = x + (size_t)b * CH * HW + pix;

    ull acc[NOUT / 2];
    #pragma unroll
    for (int j = 0; j < NOUT / 2; j++) acc[j] = 0ull;

    #pragma unroll 8
    for (int c = 0; c < CH; c++) {
        ull X = pack2(xp[c * HW]);
        const float* wr = &sW[c * NOUT];
        #pragma unroll
        for (int j = 0; j < NOUT / 4; j++) {
            ulonglong2 w = *(const ulonglong2*)(wr + j * 4);
            fma2(acc[2*j],     w.x, X);
            fma2(acc[2*j + 1], w.y, X);
        }
    }

    float vals[NOUT];
    #pragma unroll
    for (int j = 0; j < NOUT / 2; j++) {
        float2 f = unpack2(acc[j]);
        vals[2*j] = f.x; vals[2*j + 1] = f.y;
    }
    #pragma unroll
    for (int o = 0; o < NOUT; o++) {
        vals[o] = fmaxf(vals[o], __shfl_xor_sync(0xffffffffu, vals[o], 1));
        vals[o] = fmaxf(vals[o], __shfl_xor_sync(0xffffffffu, vals[o], 2));
    }
    if (sub == 0) {
        float* outp = (WSEL == 0) ? &d_phi[(size_t)pooled * CQ + ochOff]
                                  : &d_g[(size_t)pooled * CV + ochOff];
        #pragma unroll
        for (int o = 0; o < NOUT; o += 4)
            *(float4*)&outp[o] = make_float4(vals[o], vals[o+1], vals[o+2], vals[o+3]);
    }
}

// ---------------- attention: mma.sync tf32 flash kernel, cp.async double-buffered ----
// Block: 256 threads / 8 warps; 128 queries per block (warp = 16 query rows).
// K chunk [64x16] f32 bits in smem (stride 20), V chunk [64x64] (stride 72), 2 stages.
#define SKS 20
#define SVS 72
#define KSTG (64 * SKS)
#define VSTG (64 * SVS)
__global__ __launch_bounds__(256, 2) void attn_mma_kernel() {
    __shared__ unsigned sK[2 * KSTG];   // 10.0 KB
    __shared__ unsigned sV[2 * VSTG];   // 36.9 KB
    const int tid = threadIdx.x;
    const int w = tid >> 5, lane = tid & 31;
    const int g = lane >> 2, l = lane & 3;
    const int qbase = blockIdx.x * 128 + w * 16;
    const int b = (int)((blockIdx.x * 128) >> 12);
    const float* phib = &d_phi[(size_t)(b << 10) * CQ];
    const float* gb   = &d_g[(size_t)(b << 10) * CV];

    // per-thread cp.async source/dest (fixed across chunks except c0 offset)
    const int krow = tid >> 2, kseg = tid & 3;
    unsigned kdst;
    {
        unsigned base = (unsigned)__cvta_generic_to_shared(sK);
        kdst = base + (unsigned)((krow * SKS + kseg * 4) * 4);
    }
    unsigned vdst0;
    {
        unsigned base = (unsigned)__cvta_generic_to_shared(sV);
        vdst0 = base;
    }

    // Q fragments (A operand, 2 k-steps), tf32 (rna)
    unsigned qf[2][4];
    {
        const float* q0 = &d_theta[(size_t)(qbase + g) * CQ];
        const float* q1 = &d_theta[(size_t)(qbase + g + 8) * CQ];
        qf[0][0] = to_tf32(q0[l]);      qf[0][1] = to_tf32(q1[l]);
        qf[0][2] = to_tf32(q0[l + 4]);  qf[0][3] = to_tf32(q1[l + 4]);
        qf[1][0] = to_tf32(q0[8 + l]);  qf[1][1] = to_tf32(q1[8 + l]);
        qf[1][2] = to_tf32(q0[12 + l]); qf[1][3] = to_tf32(q1[12 + l]);
    }

    float o[8][4];
    #pragma unroll
    for (int nt = 0; nt < 8; nt++)
        #pragma unroll
        for (int j = 0; j < 4; j++) o[nt][j] = 0.f;
    float mA = NEG_INF, mB = NEG_INF, lA = 0.f, lB = 0.f;

    const unsigned s1 = (lane & ~3u) | ((unsigned)l >> 1);
    const unsigned s2 = s1 + 2;

    // ---- prologue: fill stage 0 ----
    {
        cp16(kdst, phib + krow * CQ + kseg * 4);
        #pragma unroll
        for (int r = 0; r < 4; r++) {
            int idx = tid + r * 256;
            int vrow = idx >> 4, vseg = idx & 15;
            cp16(vdst0 + (unsigned)((vrow * SVS + vseg * 4) * 4),
                 gb + vrow * CV + vseg * 4);
        }
        cp_commit();
        cp_wait0();
        __syncthreads();
    }

    for (int c0 = 0; c0 < TT; c0 += 64) {
        int stage = (c0 >> 6) & 1;
        const unsigned* cK = sK + stage * KSTG;
        const unsigned* cV = sV + stage * VSTG;

        // issue next-stage fill
        if (c0 + 64 < TT) {
            int nxt = stage ^ 1;
            int cn = c0 + 64;
            cp16(kdst + (unsigned)(nxt * KSTG * 4), phib + (cn + krow) * CQ + kseg * 4);
            unsigned vbase = vdst0 + (unsigned)(nxt * VSTG * 4);
            #pragma unroll
            for (int r = 0; r < 4; r++) {
                int idx = tid + r * 256;
                int vrow = idx >> 4, vseg = idx & 15;
                cp16(vbase + (unsigned)((vrow * SVS + vseg * 4) * 4),
                     gb + (cn + vrow) * CV + vseg * 4);
            }
            cp_commit();
        }

        // ---- S = Q @ K^T : 8 n-tiles x 2 k-steps ----
        float c[8][4];
        #pragma unroll
        for (int nt = 0; nt < 8; nt++) {
            c[nt][0] = c[nt][1] = c[nt][2] = c[nt][3] = 0.f;
            int kr = (nt * 8 + g) * SKS;
            mma8(c[nt], qf[0], cK[kr + l],     cK[kr + l + 4]);
            mma8(c[nt], qf[1], cK[kr + 8 + l], cK[kr + 12 + l]);
        }

        // ---- online softmax ----
        float cmA = NEG_INF, cmB = NEG_INF;
        #pragma unroll
        for (int nt = 0; nt < 8; nt++) {
            cmA = fmaxf(cmA, fmaxf(c[nt][0], c[nt][1]));
            cmB = fmaxf(cmB, fmaxf(c[nt][2], c[nt][3]));
        }
        cmA = fmaxf(cmA, __shfl_xor_sync(0xffffffffu, cmA, 1));
        cmA = fmaxf(cmA, __shfl_xor_sync(0xffffffffu, cmA, 2));
        cmB = fmaxf(cmB, __shfl_xor_sync(0xffffffffu, cmB, 1));
        cmB = fmaxf(cmB, __shfl_xor_sync(0xffffffffu, cmB, 2));
        float nmA = fmaxf(mA, cmA), nmB = fmaxf(mB, cmB);
        float sA = __expf(mA - nmA), sB = __expf(mB - nmB);
        mA = nmA; mB = nmB;
        lA *= sA; lB *= sB;

        unsigned p[8][4];
        #pragma unroll
        for (int nt = 0; nt < 8; nt++) {
            o[nt][0] *= sA; o[nt][1] *= sA; o[nt][2] *= sB; o[nt][3] *= sB;
            float p0 = __expf(c[nt][0] - mA);
            float p1 = __expf(c[nt][1] - mA);
            float p2 = __expf(c[nt][2] - mB);
            float p3 = __expf(c[nt][3] - mB);
            lA += p0 + p1; lB += p2 + p3;
            p[nt][0] = to_tf32(p0); p[nt][1] = to_tf32(p1);
            p[nt][2] = to_tf32(p2); p[nt][3] = to_tf32(p3);
        }

        // ---- O += P @ V : 8 k-blocks x 8 n-tiles ----
        #pragma unroll
        for (int kb = 0; kb < 8; kb++) {
            unsigned x0 = __shfl_sync(0xffffffffu, p[kb][0], s1);
            unsigned x1 = __shfl_sync(0xffffffffu, p[kb][1], s1);
            unsigned x2 = __shfl_sync(0xffffffffu, p[kb][2], s1);
            unsigned x3 = __shfl_sync(0xffffffffu, p[kb][3], s1);
            unsigned y0 = __shfl_sync(0xffffffffu, p[kb][0], s2);
            unsigned y1 = __shfl_sync(0xffffffffu, p[kb][1], s2);
            unsigned y2 = __shfl_sync(0xffffffffu, p[kb][2], s2);
            unsigned y3 = __shfl_sync(0xffffffffu, p[kb][3], s2);
            unsigned a[4];
            bool odd = (l & 1);
            a[0] = odd ? x1 : x0;   // P[g][kb*8 + l]
            a[1] = odd ? x3 : x2;   // P[g+8][kb*8 + l]
            a[2] = odd ? y1 : y0;   // P[g][kb*8 + l + 4]
            a[3] = odd ? y3 : y2;   // P[g+8][kb*8 + l + 4]
            int vr0 = (kb * 8 + l) * SVS;
            int vr1 = (kb * 8 + l + 4) * SVS;
            #pragma unroll
            for (int nt = 0; nt < 8; nt++) {
                mma8(o[nt], a, cV[vr0 + nt * 8 + g], cV[vr1 + nt * 8 + g]);
            }
        }

        cp_wait0();
        __syncthreads();
    }

    // final normalize + store
    lA += __shfl_xor_sync(0xffffffffu, lA, 1);
    lA += __shfl_xor_sync(0xffffffffu, lA, 2);
    lB += __shfl_xor_sync(0xffffffffu, lB, 1);
    lB += __shfl_xor_sync(0xffffffffu, lB, 2);
    float iA = 1.f / lA, iB = 1.f / lB;
    #pragma unroll
    for (int nt = 0; nt < 8; nt++) {
        float2 r0 = make_float2(o[nt][0] * iA, o[nt][1] * iA);
        float2 r1 = make_float2(o[nt][2] * iB, o[nt][3] * iB);
        *(float2*)&d_o[(size_t)(qbase + g) * CV + nt * 8 + 2 * l] = r0;
        *(float2*)&d_o[(size_t)(qbase + g + 8) * CV + nt * 8 + 2 * l] = r1;
    }
}

// ---------------- output conv + residual: out = gamma * Wo @ o + x ----------------
__global__ __launch_bounds__(256) void oconv_kernel(const float* __restrict__ x,
                                                    const float* __restrict__ gptr,
                                                    float* __restrict__ out) {
    __shared__ float sW[CV * 32];   // transposed [c][j]
    int gy = blockIdx.y;
    for (int i = threadIdx.x; i < CV * 32; i += 256) {
        int c = i >> 5, j = i & 31;
        sW[c * 32 + j] = g_Wo[(32 * gy + j) * CV + c];
    }
    __syncthreads();
    float gamma = *gptr;
    int p = blockIdx.x * 256 + threadIdx.x;
    int b = p >> 12, s = p & 4095;
    const float4* op = (const float4*)&d_o[(size_t)p * CV];

    ull acc[16];
    #pragma unroll
    for (int j = 0; j < 16; j++) acc[j] = 0ull;

    #pragma unroll 4
    for (int c4 = 0; c4 < 16; c4++) {
        float4 xv = op[c4];
        float vals[4] = {xv.x, xv.y, xv.z, xv.w};
        #pragma unroll
        for (int cc = 0; cc < 4; cc++) {
            int c = c4 * 4 + cc;
            ull X = pack2(vals[cc]);
            const float* wr = &sW[c * 32];
            #pragma unroll
            for (int j = 0; j < 8; j++) {
                ulonglong2 w = *(const ulonglong2*)(wr + j * 4);
                fma2(acc[2*j],     w.x, X);
                fma2(acc[2*j + 1], w.y, X);
            }
        }
    }
    size_t base = ((size_t)(b * CH + 32 * gy)) * HW + s;
    #pragma unroll
    for (int j = 0; j < 16; j++) {
        float2 a = unpack2(acc[j]);
        size_t i0 = base + (size_t)(2 * j) * HW;
        size_t i1 = base + (size_t)(2 * j + 1) * HW;
        out[i0] = gamma * a.x + x[i0];
        out[i1] = gamma * a.y + x[i1];
    }
}

// ---------------- launch ----------------
extern "C" void kernel_launch(void* const* d_in, const int* in_sizes, int n_in,
                              void* d_out, int out_size) {
    const float* x       = (const float*)d_in[0];
    const float* w_theta = (const float*)d_in[1];
    const float* w_phi   = (const float*)d_in[2];
    const float* w_g     = (const float*)d_in[3];
    const float* w_o     = (const float*)d_in[4];
    const float* u_theta = (const float*)d_in[5];
    const float* u_phi   = (const float*)d_in[6];
    const float* u_g     = (const float*)d_in[7];
    const float* u_o     = (const float*)d_in[8];
    const float* gamma   = (const float*)d_in[9];
    float* out = (float*)d_out;

    sn_kernel<<<4, 128>>>(w_theta, w_phi, w_g, w_o, u_theta, u_phi, u_g, u_o);
    theta_kernel<<<256, 256>>>(x);
    poolconv_kernel<16, 0><<<dim3(512, 1), 128>>>(x);
    poolconv_kernel<32, 1><<<dim3(512, 2), 128>>>(x);
    attn_mma_kernel<<<512, 256>>>();
    oconv_kernel<<<dim3(256, 4), 256>>>(x, gamma, out);
}

// round 6
// speedup vs baseline: 1.1620x; 1.1620x over previous
#include <cuda_runtime.h>
#include <cuda_fp16.h>
#include <cstdint>

#define BATCH 16
#define CH    128
#define HH    64
#define WW    64
#define HW    4096
#define CQ    16
#define CV    64
#define TT    1024
#define NEG_INF (-3.402823466e38f)

typedef unsigned long long ull;
typedef unsigned int u32;

// ---------------- scratch ----------------
__device__ float g_Wt[CQ * CH];
__device__ float g_Wp[CQ * CH];
__device__ float g_Wg[CV * CH];
__device__ float g_Wo[CH * CV];

__device__ float  d_theta[BATCH * HW * CQ];   // [b][s][16] f32
__device__ __half d_phi_h[BATCH * TT * CQ];   // [b][t][16] fp16
__device__ __half d_gT_h[BATCH * CV * TT];    // [b][c][t]  fp16 (transposed!)
__device__ float  d_o[BATCH * HW * CV];       // [b][s][64]

// ---------------- packed f32x2 helpers ----------------
__device__ __forceinline__ ull pack2(float v) {
    ull r; u32 u = __float_as_uint(v);
    asm("mov.b64 %0, {%1, %1};" : "=l"(r) : "r"(u));
    return r;
}
__device__ __forceinline__ void fma2(ull& d, ull a, ull b) {
    asm("fma.rn.f32x2 %0, %1, %2, %0;" : "+l"(d) : "l"(a), "l"(b));
}
__device__ __forceinline__ float2 unpack2(ull v) {
    float2 r;
    r.x = __uint_as_float((u32)(v & 0xffffffffull));
    r.y = __uint_as_float((u32)(v >> 32));
    return r;
}
__device__ __forceinline__ u32 h2u(float a, float b) {
    __half2 h = __floats2half2_rn(a, b);
    return *reinterpret_cast<u32*>(&h);
}

// fp16 mma m16n8k16, f32 accumulate
__device__ __forceinline__ void mmaf16(float c[4], const u32 a[4], u32 b0, u32 b1) {
    asm("mma.sync.aligned.m16n8k16.row.col.f32.f16.f16.f32 "
        "{%0,%1,%2,%3}, {%4,%5,%6,%7}, {%8,%9}, {%0,%1,%2,%3};"
        : "+f"(c[0]), "+f"(c[1]), "+f"(c[2]), "+f"(c[3])
        : "r"(a[0]), "r"(a[1]), "r"(a[2]), "r"(a[3]), "r"(b0), "r"(b1));
}

__device__ __forceinline__ void cp16(u32 dst, const void* src) {
    asm volatile("cp.async.ca.shared.global [%0], [%1], 16;" :: "r"(dst), "l"(src));
}
__device__ __forceinline__ void cp_commit() { asm volatile("cp.async.commit_group;"); }
__device__ __forceinline__ void cp_wait0()  { asm volatile("cp.async.wait_group 0;" ::: "memory"); }

// ---------------- spectral norm ----------------
__device__ __forceinline__ float block_reduce_sum_128(float v, float* sred) {
    int t = threadIdx.x;
    sred[t] = v;
    __syncthreads();
    #pragma unroll
    for (int s = 64; s > 0; s >>= 1) {
        if (t < s) sred[t] += sred[t + s];
        __syncthreads();
    }
    float r = sred[0];
    __syncthreads();
    return r;
}

__global__ void sn_kernel(const float* w_theta, const float* w_phi,
                          const float* w_g, const float* w_o,
                          const float* u_theta, const float* u_phi,
                          const float* u_g, const float* u_o) {
    __shared__ float sv[128];
    __shared__ float sred[128];
    const float* W; const float* u; float* Wn; int O, I;
    switch (blockIdx.x) {
        case 0:  W = w_theta; u = u_theta; Wn = g_Wt; O = CQ; I = CH; break;
        case 1:  W = w_phi;   u = u_phi;   Wn = g_Wp; O = CQ; I = CH; break;
        case 2:  W = w_g;     u = u_g;     Wn = g_Wg; O = CV; I = CH; break;
        default: W = w_o;     u = u_o;     Wn = g_Wo; O = CH; I = CV; break;
    }
    int t = threadIdx.x;
    float vr = 0.f;
    if (t < I) { for (int o = 0; o < O; o++) vr += u[o] * W[o * I + t]; }
    float nv2 = block_reduce_sum_128((t < I) ? vr * vr : 0.f, sred);
    float inv = 1.f / fmaxf(sqrtf(nv2), 1e-12f);
    if (t < I) sv[t] = vr * inv;
    __syncthreads();
    float ur = 0.f;
    if (t < O) { for (int i = 0; i < I; i++) ur += sv[i] * W[t * I + i]; }
    float nu2 = block_reduce_sum_128((t < O) ? ur * ur : 0.f, sred);
    float invu = 1.f / fmaxf(sqrtf(nu2), 1e-12f);
    float sigma = block_reduce_sum_128((t < O) ? ur * ur * invu : 0.f, sred);
    float wscale = 1.f / sigma;
    for (int k = t; k < O * I; k += 128) Wn[k] = W[k] * wscale;
}

// ---------------- theta conv ----------------
__global__ __launch_bounds__(256) void theta_kernel(const float* __restrict__ x) {
    __shared__ float sW[CH * CQ];   // [c][o]
    for (int i = threadIdx.x; i < CH * CQ; i += 256) {
        int c = i >> 4, o = i & 15;
        sW[i] = g_Wt[o * CH + c];
    }
    __syncthreads();
    int p = blockIdx.x * 256 + threadIdx.x;
    int b = p >> 12, s = p & 4095;
    const float* xp = x + (size_t)b * CH * HW + s;
    ull acc[8];
    #pragma unroll
    for (int j = 0; j < 8; j++) acc[j] = 0ull;
    #pragma unroll 8
    for (int c = 0; c < CH; c++) {
        ull X = pack2(xp[c * HW]);
        const float* wr = &sW[c * CQ];
        #pragma unroll
        for (int j = 0; j < 4; j++) {
            ulonglong2 w = *(const ulonglong2*)(wr + j * 4);
            fma2(acc[2*j],     w.x, X);
            fma2(acc[2*j + 1], w.y, X);
        }
    }
    float4* outp = (float4*)&d_theta[(size_t)p * CQ];
    #pragma unroll
    for (int j = 0; j < 4; j++) {
        float2 a0 = unpack2(acc[2*j]);
        float2 a1 = unpack2(acc[2*j + 1]);
        outp[j] = make_float4(a0.x, a0.y, a1.x, a1.y);
    }
}

// ---------------- pooled convs ----------------
template <int NOUT, int WSEL>
__global__ __launch_bounds__(128) void poolconv_kernel(const float* __restrict__ x) {
    __shared__ float sW[CH * NOUT];  // [c][o]
    int ochOff = blockIdx.y * NOUT;
    const float* Wsrc = (WSEL == 0 ? g_Wp : g_Wg);
    for (int i = threadIdx.x; i < CH * NOUT; i += 128) {
        int c = i / NOUT, o = i % NOUT;
        sW[i] = Wsrc[(ochOff + o) * CH + c];
    }
    __syncthreads();
    int tid = blockIdx.x * 128 + threadIdx.x;
    int pooled = tid >> 2, sub = tid & 3;
    int b = pooled >> 10, t = pooled & 1023;
    int hp = t >> 5, wp = t & 31;
    int pix = (2 * hp + (sub >> 1)) * WW + 2 * wp + (sub & 1);
    const float* xp = x + (size_t)b * CH * HW + pix;

    ull acc[NOUT / 2];
    #pragma unroll
    for (int j = 0; j < NOUT / 2; j++) acc[j] = 0ull;
    #pragma unroll 8
    for (int c = 0; c < CH; c++) {
        ull X = pack2(xp[c * HW]);
        const float* wr = &sW[c * NOUT];
        #pragma unroll
        for (int j = 0; j < NOUT / 4; j++) {
            ulonglong2 w = *(const ulonglong2*)(wr + j * 4);
            fma2(acc[2*j],     w.x, X);
            fma2(acc[2*j + 1], w.y, X);
        }
    }
    float vals[NOUT];
    #pragma unroll
    for (int j = 0; j < NOUT / 2; j++) {
        float2 f = unpack2(acc[j]);
        vals[2*j] = f.x; vals[2*j + 1] = f.y;
    }
    #pragma unroll
    for (int o = 0; o < NOUT; o++) {
        vals[o] = fmaxf(vals[o], __shfl_xor_sync(0xffffffffu, vals[o], 1));
        vals[o] = fmaxf(vals[o], __shfl_xor_sync(0xffffffffu, vals[o], 2));
    }
    if (sub == 0) {
        if (WSEL == 0) {
            // fp16 K rows [pooled][16]
            u32 pk[8];
            #pragma unroll
            for (int j = 0; j < 8; j++) pk[j] = h2u(vals[2*j], vals[2*j+1]);
            uint4* outp = (uint4*)&d_phi_h[(size_t)pooled * CQ];
            outp[0] = make_uint4(pk[0], pk[1], pk[2], pk[3]);
            outp[1] = make_uint4(pk[4], pk[5], pk[6], pk[7]);
        } else {
            // fp16 V transposed [b][c][t]
            #pragma unroll
            for (int o = 0; o < NOUT; o++)
                d_gT_h[((size_t)b * CV + ochOff + o) * TT + t] = __float2half_rn(vals[o]);
        }
    }
}

// ---------------- attention: fp16 m16n8k16 flash, cp.async double-buffered ----
// K stage: 64 rows x 8 words (16 halfs). V_T stage: 64 ch-rows x 36 words (72 halfs, 64 used).
#define KSW 8
#define VSW 36
#define KSTG (64 * KSW)
#define VSTG (64 * VSW)
__global__ __launch_bounds__(256, 2) void attn_mma_kernel() {
    __shared__ u32 sK[2 * KSTG];   // 4 KB
    __shared__ u32 sV[2 * VSTG];   // 18 KB
    const int tid = threadIdx.x;
    const int w = tid >> 5, lane = tid & 31;
    const int g = lane >> 2, l = lane & 3;
    const int qbase = blockIdx.x * 128 + w * 16;
    const int b = (int)((blockIdx.x * 128) >> 12);
    const __half* phib = &d_phi_h[(size_t)(b << 10) * CQ];
    const __half* gTb  = &d_gT_h[(size_t)b * CV * TT];

    const u32 kbase = (u32)__cvta_generic_to_shared(sK);
    const u32 vbase = (u32)__cvta_generic_to_shared(sV);

    // Q fragment fp16 (single k=16 step)
    u32 qh[4];
    {
        const float* q0 = &d_theta[(size_t)(qbase + g) * CQ];
        const float* q1 = &d_theta[(size_t)(qbase + g + 8) * CQ];
        qh[0] = h2u(q0[2*l],     q0[2*l + 1]);
        qh[1] = h2u(q1[2*l],     q1[2*l + 1]);
        qh[2] = h2u(q0[2*l + 8], q0[2*l + 9]);
        qh[3] = h2u(q1[2*l + 8], q1[2*l + 9]);
    }

    float o[8][4];
    #pragma unroll
    for (int nt = 0; nt < 8; nt++)
        #pragma unroll
        for (int j = 0; j < 4; j++) o[nt][j] = 0.f;
    float mA = NEG_INF, mB = NEG_INF, lA = 0.f, lB = 0.f;

    // fill helpers: K = 128 cp16 (tid<128), V = 512 cp16 (2/thread)
    auto fill = [&](int stage, int c0) {
        if (tid < 128) {
            int row = tid >> 1, part = tid & 1;
            cp16(kbase + (u32)((stage * KSTG + row * KSW + part * 4) * 4),
                 phib + (c0 + row) * CQ + part * 8);
        }
        #pragma unroll
        for (int i = 0; i < 2; i++) {
            int idx = tid * 2 + i;
            int c = idx >> 3, t8 = idx & 7;
            cp16(vbase + (u32)((stage * VSTG + c * VSW + t8 * 4) * 4),
                 gTb + (size_t)c * TT + c0 + t8 * 8);
        }
        cp_commit();
    };

    fill(0, 0);
    cp_wait0();
    __syncthreads();

    for (int c0 = 0; c0 < TT; c0 += 64) {
        int stage = (c0 >> 6) & 1;
        const u32* cK = sK + stage * KSTG;
        const u32* cV = sV + stage * VSTG;

        if (c0 + 64 < TT) fill(stage ^ 1, c0 + 64);

        // ---- S = Q @ K^T : 8 n-tiles, one k=16 step each ----
        float c[8][4];
        #pragma unroll
        for (int nt = 0; nt < 8; nt++) {
            c[nt][0] = c[nt][1] = c[nt][2] = c[nt][3] = 0.f;
            int kr = (nt * 8 + g) * KSW;
            mmaf16(c[nt], qh, cK[kr + l], cK[kr + l + 4]);
        }

        // ---- online softmax ----
        float cmA = NEG_INF, cmB = NEG_INF;
        #pragma unroll
        for (int nt = 0; nt < 8; nt++) {
            cmA = fmaxf(cmA, fmaxf(c[nt][0], c[nt][1]));
            cmB = fmaxf(cmB, fmaxf(c[nt][2], c[nt][3]));
        }
        cmA = fmaxf(cmA, __shfl_xor_sync(0xffffffffu, cmA, 1));
        cmA = fmaxf(cmA, __shfl_xor_sync(0xffffffffu, cmA, 2));
        cmB = fmaxf(cmB, __shfl_xor_sync(0xffffffffu, cmB, 1));
        cmB = fmaxf(cmB, __shfl_xor_sync(0xffffffffu, cmB, 2));
        float nmA = fmaxf(mA, cmA), nmB = fmaxf(mB, cmB);
        float sA = __expf(mA - nmA), sB = __expf(mB - nmB);
        mA = nmA; mB = nmB;
        lA *= sA; lB *= sB;

        // P and fp16 A-fragments (no shuffles: C pairs (2kb,2kb+1) == A pairs)
        u32 pa[4][4];
        #pragma unroll
        for (int nt = 0; nt < 8; nt++) {
            o[nt][0] *= sA; o[nt][1] *= sA; o[nt][2] *= sB; o[nt][3] *= sB;
            float p0 = __expf(c[nt][0] - mA);
            float p1 = __expf(c[nt][1] - mA);
            float p2 = __expf(c[nt][2] - mB);
            float p3 = __expf(c[nt][3] - mB);
            lA += p0 + p1; lB += p2 + p3;
            int kb = nt >> 1, hi = nt & 1;
            pa[kb][hi * 2]     = h2u(p0, p1);
            pa[kb][hi * 2 + 1] = h2u(p2, p3);
        }

        // ---- O += P @ V : 4 k-blocks x 8 n-tiles ----
        #pragma unroll
        for (int kb = 0; kb < 4; kb++) {
            #pragma unroll
            for (int nt = 0; nt < 8; nt++) {
                int vr = (nt * 8 + g) * VSW + kb * 8 + l;
                mmaf16(o[nt], pa[kb], cV[vr], cV[vr + 4]);
            }
        }

        cp_wait0();
        __syncthreads();
    }

    lA += __shfl_xor_sync(0xffffffffu, lA, 1);
    lA += __shfl_xor_sync(0xffffffffu, lA, 2);
    lB += __shfl_xor_sync(0xffffffffu, lB, 1);
    lB += __shfl_xor_sync(0xffffffffu, lB, 2);
    float iA = 1.f / lA, iB = 1.f / lB;
    #pragma unroll
    for (int nt = 0; nt < 8; nt++) {
        float2 r0 = make_float2(o[nt][0] * iA, o[nt][1] * iA);
        float2 r1 = make_float2(o[nt][2] * iB, o[nt][3] * iB);
        *(float2*)&d_o[(size_t)(qbase + g) * CV + nt * 8 + 2 * l] = r0;
        *(float2*)&d_o[(size_t)(qbase + g + 8) * CV + nt * 8 + 2 * l] = r1;
    }
}

// ---------------- output conv + residual ----------------
__global__ __launch_bounds__(256) void oconv_kernel(const float* __restrict__ x,
                                                    const float* __restrict__ gptr,
                                                    float* __restrict__ out) {
    __shared__ float sW[CV * 32];   // [c][j]
    int gy = blockIdx.y;
    for (int i = threadIdx.x; i < CV * 32; i += 256) {
        int c = i >> 5, j = i & 31;
        sW[c * 32 + j] = g_Wo[(32 * gy + j) * CV + c];
    }
    __syncthreads();
    float gamma = *gptr;
    int p = blockIdx.x * 256 + threadIdx.x;
    int b = p >> 12, s = p & 4095;
    const float4* op = (const float4*)&d_o[(size_t)p * CV];

    ull acc[16];
    #pragma unroll
    for (int j = 0; j < 16; j++) acc[j] = 0ull;

    #pragma unroll 4
    for (int c4 = 0; c4 < 16; c4++) {
        float4 xv = op[c4];
        float vals[4] = {xv.x, xv.y, xv.z, xv.w};
        #pragma unroll
        for (int cc = 0; cc < 4; cc++) {
            int c = c4 * 4 + cc;
            ull X = pack2(vals[cc]);
            const float* wr = &sW[c * 32];
            #pragma unroll
            for (int j = 0; j < 8; j++) {
                ulonglong2 w = *(const ulonglong2*)(wr + j * 4);
                fma2(acc[2*j],     w.x, X);
                fma2(acc[2*j + 1], w.y, X);
            }
        }
    }
    size_t base = ((size_t)(b * CH + 32 * gy)) * HW + s;
    #pragma unroll
    for (int j = 0; j < 16; j++) {
        float2 a = unpack2(acc[j]);
        size_t i0 = base + (size_t)(2 * j) * HW;
        size_t i1 = base + (size_t)(2 * j + 1) * HW;
        out[i0] = gamma * a.x + x[i0];
        out[i1] = gamma * a.y + x[i1];
    }
}

// ---------------- launch ----------------
extern "C" void kernel_launch(void* const* d_in, const int* in_sizes, int n_in,
                              void* d_out, int out_size) {
    const float* x       = (const float*)d_in[0];
    const float* w_theta = (const float*)d_in[1];
    const float* w_phi   = (const float*)d_in[2];
    const float* w_g     = (const float*)d_in[3];
    const float* w_o     = (const float*)d_in[4];
    const float* u_theta = (const float*)d_in[5];
    const float* u_phi   = (const float*)d_in[6];
    const float* u_g     = (const float*)d_in[7];
    const float* u_o     = (const float*)d_in[8];
    const float* gamma   = (const float*)d_in[9];
    float* out = (float*)d_out;

    sn_kernel<<<4, 128>>>(w_theta, w_phi, w_g, w_o, u_theta, u_phi, u_g, u_o);
    theta_kernel<<<256, 256>>>(x);
    poolconv_kernel<16, 0><<<dim3(512, 1), 128>>>(x);
    poolconv_kernel<32, 1><<<dim3(512, 2), 128>>>(x);
    attn_mma_kernel<<<512, 256>>>();
    oconv_kernel<<<dim3(256, 4), 256>>>(x, gamma, out);
}

// round 8
// speedup vs baseline: 1.7063x; 1.4685x over previous
#include <cuda_runtime.h>
#include <cuda_fp16.h>
#include <cstdint>

#define BATCH 16
#define CH    128
#define HH    64
#define WW    64
#define HW    4096
#define CQ    16
#define CV    64
#define TT    1024
#define NEG_INF (-3.402823466e38f)

typedef unsigned long long ull;
typedef unsigned int u32;

// ---------------- scratch ----------------
__device__ float g_Wt[CQ * CH];
__device__ float g_Wp[CQ * CH];
__device__ float g_Wg[CV * CH];
__device__ float g_Wo[CH * CV];

__device__ __half d_theta_h[BATCH * HW * CQ];  // [b][s][16] fp16
__device__ __half d_phi_h[BATCH * TT * CQ];    // [b][t][16] fp16
__device__ __half d_gT_h[BATCH * CV * TT];     // [b][c][t]  fp16 transposed
__device__ float  d_o[BATCH * HW * CV];        // [b][s][64]

// ---------------- helpers ----------------
__device__ __forceinline__ ull pack2(float v) {
    ull r; u32 u = __float_as_uint(v);
    asm("mov.b64 %0, {%1, %1};" : "=l"(r) : "r"(u));
    return r;
}
__device__ __forceinline__ void fma2(ull& d, ull a, ull b) {
    asm("fma.rn.f32x2 %0, %1, %2, %0;" : "+l"(d) : "l"(a), "l"(b));
}
__device__ __forceinline__ float2 unpack2(ull v) {
    float2 r;
    r.x = __uint_as_float((u32)(v & 0xffffffffull));
    r.y = __uint_as_float((u32)(v >> 32));
    return r;
}
__device__ __forceinline__ u32 h2u(float a, float b) {
    __half2 h = __floats2half2_rn(a, b);
    return *reinterpret_cast<u32*>(&h);
}
__device__ __forceinline__ u32 smem_u32(const void* p) {
    u32 a;
    asm("{ .reg .u64 t; cvta.to.shared.u64 t, %1; cvt.u32.u64 %0, t; }" : "=r"(a) : "l"(p));
    return a;
}

// fp16 mma m16n8k16, f32 accumulate
__device__ __forceinline__ void mmaf16(float c[4], const u32 a[4], u32 b0, u32 b1) {
    asm("mma.sync.aligned.m16n8k16.row.col.f32.f16.f16.f32 "
        "{%0,%1,%2,%3}, {%4,%5,%6,%7}, {%8,%9}, {%0,%1,%2,%3};"
        : "+f"(c[0]), "+f"(c[1]), "+f"(c[2]), "+f"(c[3])
        : "r"(a[0]), "r"(a[1]), "r"(a[2]), "r"(a[3]), "r"(b0), "r"(b1));
}
__device__ __forceinline__ void ldm4(u32& r0, u32& r1, u32& r2, u32& r3, u32 addr) {
    asm volatile("ldmatrix.sync.aligned.m8n8.x4.shared.b16 {%0,%1,%2,%3}, [%4];"
                 : "=r"(r0), "=r"(r1), "=r"(r2), "=r"(r3) : "r"(addr));
}
__device__ __forceinline__ void ldm4t(u32& r0, u32& r1, u32& r2, u32& r3, u32 addr) {
    asm volatile("ldmatrix.sync.aligned.m8n8.x4.trans.shared.b16 {%0,%1,%2,%3}, [%4];"
                 : "=r"(r0), "=r"(r1), "=r"(r2), "=r"(r3) : "r"(addr));
}

__device__ __forceinline__ void cp16(u32 dst, const void* src) {
    asm volatile("cp.async.ca.shared.global [%0], [%1], 16;" :: "r"(dst), "l"(src));
}
__device__ __forceinline__ void cp_commit() { asm volatile("cp.async.commit_group;"); }
__device__ __forceinline__ void cp_wait0() { asm volatile("cp.async.wait_group 0;" ::: "memory"); }

// ---------------- spectral norm ----------------
__device__ __forceinline__ float block_reduce_sum_128(float v, float* sred) {
    int t = threadIdx.x;
    sred[t] = v;
    __syncthreads();
    #pragma unroll
    for (int s = 64; s > 0; s >>= 1) {
        if (t < s) sred[t] += sred[t + s];
        __syncthreads();
    }
    float r = sred[0];
    __syncthreads();
    return r;
}

__global__ void sn_kernel(const float* w_theta, const float* w_phi,
                          const float* w_g, const float* w_o,
                          const float* u_theta, const float* u_phi,
                          const float* u_g, const float* u_o) {
    __shared__ float sv[128];
    __shared__ float sred[128];
    const float* W; const float* u; float* Wn; int O, I;
    switch (blockIdx.x) {
        case 0:  W = w_theta; u = u_theta; Wn = g_Wt; O = CQ; I = CH; break;
        case 1:  W = w_phi;   u = u_phi;   Wn = g_Wp; O = CQ; I = CH; break;
        case 2:  W = w_g;     u = u_g;     Wn = g_Wg; O = CV; I = CH; break;
        default: W = w_o;     u = u_o;     Wn = g_Wo; O = CH; I = CV; break;
    }
    int t = threadIdx.x;
    float vr = 0.f;
    if (t < I) { for (int o = 0; o < O; o++) vr += u[o] * W[o * I + t]; }
    float nv2 = block_reduce_sum_128((t < I) ? vr * vr : 0.f, sred);
    float inv = 1.f / fmaxf(sqrtf(nv2), 1e-12f);
    if (t < I) sv[t] = vr * inv;
    __syncthreads();
    float ur = 0.f;
    if (t < O) { for (int i = 0; i < I; i++) ur += sv[i] * W[t * I + i]; }
    float nu2 = block_reduce_sum_128((t < O) ? ur * ur : 0.f, sred);
    float invu = 1.f / fmaxf(sqrtf(nu2), 1e-12f);
    float sigma = block_reduce_sum_128((t < O) ? ur * ur * invu : 0.f, sred);
    float wscale = 1.f / sigma;
    for (int k = t; k < O * I; k += 128) Wn[k] = W[k] * wscale;
}

// ---------------- fused input conv (theta | phi | g) via fp16 mma ----------------
// Block = (batch b, row-pair j): 128 px (image rows 2j, 2j+1), 256 threads / 8 warps.
// GEMM: A = X^T [m=128 px, k=128 ch] (ldmatrix.trans on [ch][px] smem),
//       B = W   [k=128 ch, n=96 out] (plain ldmatrix on [out][ch] smem).
// Epilogue: C -> smem bounce [px][104] -> theta rows / phi pooled / gT pooled.
#define XROW 272                     // bytes per ch row (256 + 16 pad)
#define SM_X 0
#define SM_W (128 * XROW)            // 34816
#define CONV_SMEM (SM_W + 96 * XROW) // 60928

__global__ __launch_bounds__(256) void fusedconv_kernel(const float* __restrict__ x) {
    extern __shared__ char smc[];
    const u32 sXu = smem_u32(smc) + SM_X;
    const u32 sWu = smem_u32(smc) + SM_W;
    const int tid = threadIdx.x;
    const int w = tid >> 5, lane = tid & 31;
    const int b = blockIdx.x >> 5, j = blockIdx.x & 31;
    const int s0 = j * 128;

    // ---- fill W smem: [out][128 ch] fp16, row stride 272B ----
    for (int i = tid; i < 96 * 16; i += 256) {
        int out = i >> 4, seg = i & 15;            // 8 halfs per seg
        const float* src;
        if (out < 16)      src = g_Wt + out * CH + seg * 8;
        else if (out < 32) src = g_Wp + (out - 16) * CH + seg * 8;
        else               src = g_Wg + (out - 32) * CH + seg * 8;
        float4 f0 = *(const float4*)src;
        float4 f1 = *(const float4*)(src + 4);
        uint4 v = make_uint4(h2u(f0.x, f0.y), h2u(f0.z, f0.w),
                             h2u(f1.x, f1.y), h2u(f1.z, f1.w));
        asm volatile("st.shared.v4.b32 [%0], {%1,%2,%3,%4};"
                     :: "r"(sWu + (u32)(out * XROW + seg * 16)),
                        "r"(v.x), "r"(v.y), "r"(v.z), "r"(v.w) : "memory");
    }
    // ---- fill X smem: [ch][128 px] fp16, row stride 272B ----
    for (int i = tid; i < 128 * 32; i += 256) {
        int ch = i >> 5, seg = i & 31;             // 4 px per seg
        float4 f = *(const float4*)&x[((size_t)b * CH + ch) * HW + s0 + seg * 4];
        u32 h0 = h2u(f.x, f.y), h1 = h2u(f.z, f.w);
        asm volatile("st.shared.v2.b32 [%0], {%1,%2};"
                     :: "r"(sXu + (u32)(ch * XROW + seg * 8)), "r"(h0), "r"(h1) : "memory");
    }
    __syncthreads();

    // ---- GEMM ----
    const int jj = lane & 7, grp = lane >> 3;
    // A (trans): rows = ch, col-offset = px
    const u32 aBase = sXu + (u32)((((grp & 2) ? 8 : 0) + jj) * XROW
                                  + (16 * w + ((grp & 1) ? 8 : 0)) * 2);
    // B: rows = out
    u32 bBase[6];
    #pragma unroll
    for (int np = 0; np < 6; np++)
        bBase[np] = sWu + (u32)((np * 16 + ((grp >> 1) ? 8 : 0) + jj) * XROW
                                + ((grp & 1) ? 16 : 0));

    float c[12][4];
    #pragma unroll
    for (int nt = 0; nt < 12; nt++)
        c[nt][0] = c[nt][1] = c[nt][2] = c[nt][3] = 0.f;

    #pragma unroll
    for (int t = 0; t < 8; t++) {
        u32 a[4];
        ldm4t(a[0], a[1], a[2], a[3], aBase + (u32)(t * 16 * XROW));
        #pragma unroll
        for (int np = 0; np < 6; np++) {
            u32 b0, b1, b2, b3;
            ldm4(b0, b1, b2, b3, bBase[np] + (u32)(t * 32));
            mmaf16(c[2 * np],     a, b0, b1);
            mmaf16(c[2 * np + 1], a, b2, b3);
        }
    }
    __syncthreads();    // X reads done; reuse region as C bounce [px][104 halfs]

    // ---- C -> smem bounce ----
    const int g = lane >> 2, l = lane & 3;
    const int pxA = 16 * w + g;
    #pragma unroll
    for (int nt = 0; nt < 12; nt++) {
        u32 lo = h2u(c[nt][0], c[nt][1]);
        u32 hi = h2u(c[nt][2], c[nt][3]);
        asm volatile("st.shared.b32 [%0], %1;"
                     :: "r"(sXu + (u32)((pxA * 104 + nt * 8 + 2 * l) * 2)), "r"(lo) : "memory");
        asm volatile("st.shared.b32 [%0], %1;"
                     :: "r"(sXu + (u32)(((pxA + 8) * 104 + nt * 8 + 2 * l) * 2)), "r"(hi) : "memory");
    }
    __syncthreads();

    const __half* sCh = (const __half*)smc;
    // ---- theta: outs 0-15 -> d_theta_h[b][s][16] ----
    {
        int px = tid >> 1, h = tid & 1;
        uint4 v = *(const uint4*)(sCh + px * 104 + h * 8);
        *(uint4*)&d_theta_h[((size_t)b * HW + s0 + px) * CQ + h * 8] = v;
    }
    // ---- phi: outs 16-31, 2x2 maxpool -> d_phi_h[b][t][16] ----
    if (tid < 64) {
        int wp = tid >> 1, h = tid & 1;
        int off = 16 + h * 8;
        const __half2* p0 = (const __half2*)(sCh + (2 * wp) * 104 + off);
        const __half2* p1 = (const __half2*)(sCh + (2 * wp + 1) * 104 + off);
        const __half2* p2 = (const __half2*)(sCh + (64 + 2 * wp) * 104 + off);
        const __half2* p3 = (const __half2*)(sCh + (65 + 2 * wp) * 104 + off);
        __half2 r[4];
        #pragma unroll
        for (int k = 0; k < 4; k++)
            r[k] = __hmax2(__hmax2(p0[k], p1[k]), __hmax2(p2[k], p3[k]));
        *(uint4*)&d_phi_h[((size_t)b * TT + j * 32 + wp) * CQ + h * 8] = *(uint4*)r;
    }
    // ---- g: outs 32-95, maxpool, transposed -> d_gT_h[b][c][t] ----
    if (tid < 128) {
        int ch = tid >> 1, wh = (tid & 1) * 16;
        __half2 outv[8];
        #pragma unroll
        for (int k2 = 0; k2 < 8; k2++) {
            __half v[2];
            #pragma unroll
            for (int u = 0; u < 2; u++) {
                int wp = wh + k2 * 2 + u;
                __half a0 = sCh[(2 * wp) * 104 + 32 + ch];
                __half a1 = sCh[(2 * wp + 1) * 104 + 32 + ch];
                __half a2 = sCh[(64 + 2 * wp) * 104 + 32 + ch];
                __half a3 = sCh[(65 + 2 * wp) * 104 + 32 + ch];
                v[u] = __hmax(__hmax(a0, a1), __hmax(a2, a3));
            }
            outv[k2] = __halves2half2(v[0], v[1]);
        }
        __half* dst = &d_gT_h[((size_t)b * CV + ch) * TT + j * 32 + wh];
        #pragma unroll
        for (int k2 = 0; k2 < 8; k2++) ((__half2*)dst)[k2] = outv[k2];
    }
}

// ---------------- attention: fp16 m16n8k16 flash, cp.async double-buffered ----
#define KSW 8
#define VSW 36
#define KSTG (64 * KSW)
#define VSTG (64 * VSW)
__global__ __launch_bounds__(256, 2) void attn_mma_kernel() {
    __shared__ u32 sK[2 * KSTG];
    __shared__ u32 sV[2 * VSTG];
    const int tid = threadIdx.x;
    const int w = tid >> 5, lane = tid & 31;
    const int g = lane >> 2, l = lane & 3;
    const int qbase = blockIdx.x * 128 + w * 16;
    const int b = (int)((blockIdx.x * 128) >> 12);
    const __half* phib = &d_phi_h[(size_t)(b << 10) * CQ];
    const __half* gTb  = &d_gT_h[(size_t)b * CV * TT];

    const u32 kbase = (u32)__cvta_generic_to_shared(sK);
    const u32 vbase = (u32)__cvta_generic_to_shared(sV);

    u32 qh[4];
    {
        const u32* q0 = (const u32*)&d_theta_h[(size_t)(qbase + g) * CQ];
        const u32* q1 = (const u32*)&d_theta_h[(size_t)(qbase + g + 8) * CQ];
        qh[0] = q0[l];     qh[1] = q1[l];
        qh[2] = q0[l + 4]; qh[3] = q1[l + 4];
    }

    float o[8][4];
    #pragma unroll
    for (int nt = 0; nt < 8; nt++)
        #pragma unroll
        for (int jj = 0; jj < 4; jj++) o[nt][jj] = 0.f;
    float mA = NEG_INF, mB = NEG_INF, lA = 0.f, lB = 0.f;

    auto fill = [&](int stage, int c0) {
        if (tid < 128) {
            int row = tid >> 1, part = tid & 1;
            cp16(kbase + (u32)((stage * KSTG + row * KSW + part * 4) * 4),
                 phib + (c0 + row) * CQ + part * 8);
        }
        #pragma unroll
        for (int i = 0; i < 2; i++) {
            int idx = tid * 2 + i;
            int c = idx >> 3, t8 = idx & 7;
            cp16(vbase + (u32)((stage * VSTG + c * VSW + t8 * 4) * 4),
                 gTb + (size_t)c * TT + c0 + t8 * 8);
        }
        cp_commit();
    };

    fill(0, 0);
    cp_wait0();
    __syncthreads();

    for (int c0 = 0; c0 < TT; c0 += 64) {
        int stage = (c0 >> 6) & 1;
        const u32* cK = sK + stage * KSTG;
        const u32* cV = sV + stage * VSTG;

        if (c0 + 64 < TT) fill(stage ^ 1, c0 + 64);

        float c[8][4];
        #pragma unroll
        for (int nt = 0; nt < 8; nt++) {
            c[nt][0] = c[nt][1] = c[nt][2] = c[nt][3] = 0.f;
            int kr = (nt * 8 + g) * KSW;
            mmaf16(c[nt], qh, cK[kr + l], cK[kr + l + 4]);
        }

        float cmA = NEG_INF, cmB = NEG_INF;
        #pragma unroll
        for (int nt = 0; nt < 8; nt++) {
            cmA = fmaxf(cmA, fmaxf(c[nt][0], c[nt][1]));
            cmB = fmaxf(cmB, fmaxf(c[nt][2], c[nt][3]));
        }
        cmA = fmaxf(cmA, __shfl_xor_sync(0xffffffffu, cmA, 1));
        cmA = fmaxf(cmA, __shfl_xor_sync(0xffffffffu, cmA, 2));
        cmB = fmaxf(cmB, __shfl_xor_sync(0xffffffffu, cmB, 1));
        cmB = fmaxf(cmB, __shfl_xor_sync(0xffffffffu, cmB, 2));
        float nmA = fmaxf(mA, cmA), nmB = fmaxf(mB, cmB);
        float sA = __expf(mA - nmA), sB = __expf(mB - nmB);
        mA = nmA; mB = nmB;
        lA *= sA; lB *= sB;

        u32 pa[4][4];
        #pragma unroll
        for (int nt = 0; nt < 8; nt++) {
            o[nt][0] *= sA; o[nt][1] *= sA; o[nt][2] *= sB; o[nt][3] *= sB;
            float p0 = __expf(c[nt][0] - mA);
            float p1 = __expf(c[nt][1] - mA);
            float p2 = __expf(c[nt][2] - mB);
            float p3 = __expf(c[nt][3] - mB);
            lA += p0 + p1; lB += p2 + p3;
            int kb = nt >> 1, hi = nt & 1;
            pa[kb][hi * 2]     = h2u(p0, p1);
            pa[kb][hi * 2 + 1] = h2u(p2, p3);
        }

        #pragma unroll
        for (int kb = 0; kb < 4; kb++) {
            #pragma unroll
            for (int nt = 0; nt < 8; nt++) {
                int vr = (nt * 8 + g) * VSW + kb * 8 + l;
                mmaf16(o[nt], pa[kb], cV[vr], cV[vr + 4]);
            }
        }

        cp_wait0();
        __syncthreads();
    }

    lA += __shfl_xor_sync(0xffffffffu, lA, 1);
    lA += __shfl_xor_sync(0xffffffffu, lA, 2);
    lB += __shfl_xor_sync(0xffffffffu, lB, 1);
    lB += __shfl_xor_sync(0xffffffffu, lB, 2);
    float iA = 1.f / lA, iB = 1.f / lB;
    #pragma unroll
    for (int nt = 0; nt < 8; nt++) {
        float2 r0 = make_float2(o[nt][0] * iA, o[nt][1] * iA);
        float2 r1 = make_float2(o[nt][2] * iB, o[nt][3] * iB);
        *(float2*)&d_o[(size_t)(qbase + g) * CV + nt * 8 + 2 * l] = r0;
        *(float2*)&d_o[(size_t)(qbase + g + 8) * CV + nt * 8 + 2 * l] = r1;
    }
}

// ---------------- output conv + residual ----------------
__global__ __launch_bounds__(256) void oconv_kernel(const float* __restrict__ x,
                                                    const float* __restrict__ gptr,
                                                    float* __restrict__ out) {
    __shared__ float sW[CV * 32];
    int gy = blockIdx.y;
    for (int i = threadIdx.x; i < CV * 32; i += 256) {
        int c = i >> 5, jj = i & 31;
        sW[c * 32 + jj] = g_Wo[(32 * gy + jj) * CV + c];
    }
    __syncthreads();
    float gamma = *gptr;
    int p = blockIdx.x * 256 + threadIdx.x;
    int b = p >> 12, s = p & 4095;
    const float4* op = (const float4*)&d_o[(size_t)p * CV];

    ull acc[16];
    #pragma unroll
    for (int jj = 0; jj < 16; jj++) acc[jj] = 0ull;

    #pragma unroll 4
    for (int c4 = 0; c4 < 16; c4++) {
        float4 xv = op[c4];
        float vals[4] = {xv.x, xv.y, xv.z, xv.w};
        #pragma unroll
        for (int cc = 0; cc < 4; cc++) {
            int c = c4 * 4 + cc;
            ull X = pack2(vals[cc]);
            const float* wr = &sW[c * 32];
            #pragma unroll
            for (int jj = 0; jj < 8; jj++) {
                ulonglong2 wv = *(const ulonglong2*)(wr + jj * 4);
                fma2(acc[2*jj],     wv.x, X);
                fma2(acc[2*jj + 1], wv.y, X);
            }
        }
    }
    size_t base = ((size_t)(b * CH + 32 * gy)) * HW + s;
    #pragma unroll
    for (int jj = 0; jj < 16; jj++) {
        float2 a = unpack2(acc[jj]);
        size_t i0 = base + (size_t)(2 * jj) * HW;
        size_t i1 = base + (size_t)(2 * jj + 1) * HW;
        out[i0] = gamma * a.x + x[i0];
        out[i1] = gamma * a.y + x[i1];
    }
}

// ---------------- launch ----------------
extern "C" void kernel_launch(void* const* d_in, const int* in_sizes, int n_in,
                              void* d_out, int out_size) {
    const float* x       = (const float*)d_in[0];
    const float* w_theta = (const float*)d_in[1];
    const float* w_phi   = (const float*)d_in[2];
    const float* w_g     = (const float*)d_in[3];
    const float* w_o     = (const float*)d_in[4];
    const float* u_theta = (const float*)d_in[5];
    const float* u_phi   = (const float*)d_in[6];
    const float* u_g     = (const float*)d_in[7];
    const float* u_o     = (const float*)d_in[8];
    const float* gamma   = (const float*)d_in[9];
    float* out = (float*)d_out;

    cudaFuncSetAttribute(fusedconv_kernel, cudaFuncAttributeMaxDynamicSharedMemorySize, CONV_SMEM);

    sn_kernel<<<4, 128>>>(w_theta, w_phi, w_g, w_o, u_theta, u_phi, u_g, u_o);
    fusedconv_kernel<<<512, 256, CONV_SMEM>>>(x);
    attn_mma_kernel<<<512, 256>>>();
    oconv_kernel<<<dim3(256, 4), 256>>>(x, gamma, out);
}

// round 9
// speedup vs baseline: 2.5593x; 1.4999x over previous
#include <cuda_runtime.h>
#include <cuda_fp16.h>
#include <cstdint>

#define BATCH 16
#define CH    128
#define HH    64
#define WW    64
#define HW    4096
#define CQ    16
#define CV    64
#define TT    1024
#define NEG_INF (-3.402823466e38f)

typedef unsigned long long ull;
typedef unsigned int u32;

// ---------------- scratch ----------------
__device__ float g_Wt[CQ * CH];
__device__ float g_Wp[CQ * CH];
__device__ float g_Wg[CV * CH];
__device__ float g_Wo[CH * CV];

__device__ __half d_theta_h[BATCH * HW * CQ];  // [b][s][16] fp16
__device__ __half d_phi_h[BATCH * TT * CQ];    // [b][t][16] fp16
__device__ __half d_gT_h[BATCH * CV * TT];     // [b][c][t]  fp16 transposed
__device__ __half d_o_h[BATCH * HW * CV];      // [b][s][64] fp16

// ---------------- helpers ----------------
__device__ __forceinline__ ull pack2(float v) {
    ull r; u32 u = __float_as_uint(v);
    asm("mov.b64 %0, {%1, %1};" : "=l"(r) : "r"(u));
    return r;
}
__device__ __forceinline__ void fma2(ull& d, ull a, ull b) {
    asm("fma.rn.f32x2 %0, %1, %2, %0;" : "+l"(d) : "l"(a), "l"(b));
}
__device__ __forceinline__ float2 unpack2(ull v) {
    float2 r;
    r.x = __uint_as_float((u32)(v & 0xffffffffull));
    r.y = __uint_as_float((u32)(v >> 32));
    return r;
}
__device__ __forceinline__ u32 h2u(float a, float b) {
    __half2 h = __floats2half2_rn(a, b);
    return *reinterpret_cast<u32*>(&h);
}
__device__ __forceinline__ u32 smem_u32(const void* p) {
    u32 a;
    asm("{ .reg .u64 t; cvta.to.shared.u64 t, %1; cvt.u32.u64 %0, t; }" : "=r"(a) : "l"(p));
    return a;
}

// fp16 mma m16n8k16, f32 accumulate
__device__ __forceinline__ void mmaf16(float c[4], const u32 a[4], u32 b0, u32 b1) {
    asm("mma.sync.aligned.m16n8k16.row.col.f32.f16.f16.f32 "
        "{%0,%1,%2,%3}, {%4,%5,%6,%7}, {%8,%9}, {%0,%1,%2,%3};"
        : "+f"(c[0]), "+f"(c[1]), "+f"(c[2]), "+f"(c[3])
        : "r"(a[0]), "r"(a[1]), "r"(a[2]), "r"(a[3]), "r"(b0), "r"(b1));
}
__device__ __forceinline__ void ldm4(u32& r0, u32& r1, u32& r2, u32& r3, u32 addr) {
    asm volatile("ldmatrix.sync.aligned.m8n8.x4.shared.b16 {%0,%1,%2,%3}, [%4];"
                 : "=r"(r0), "=r"(r1), "=r"(r2), "=r"(r3) : "r"(addr));
}
__device__ __forceinline__ void ldm4t(u32& r0, u32& r1, u32& r2, u32& r3, u32 addr) {
    asm volatile("ldmatrix.sync.aligned.m8n8.x4.trans.shared.b16 {%0,%1,%2,%3}, [%4];"
                 : "=r"(r0), "=r"(r1), "=r"(r2), "=r"(r3) : "r"(addr));
}

__device__ __forceinline__ void cp16(u32 dst, const void* src) {
    asm volatile("cp.async.ca.shared.global [%0], [%1], 16;" :: "r"(dst), "l"(src));
}
__device__ __forceinline__ void cp_commit() { asm volatile("cp.async.commit_group;"); }
__device__ __forceinline__ void cp_wait0() { asm volatile("cp.async.wait_group 0;" ::: "memory"); }

// ---------------- spectral norm ----------------
__device__ __forceinline__ float block_reduce_sum_128(float v, float* sred) {
    int t = threadIdx.x;
    sred[t] = v;
    __syncthreads();
    #pragma unroll
    for (int s = 64; s > 0; s >>= 1) {
        if (t < s) sred[t] += sred[t + s];
        __syncthreads();
    }
    float r = sred[0];
    __syncthreads();
    return r;
}

__global__ void sn_kernel(const float* w_theta, const float* w_phi,
                          const float* w_g, const float* w_o,
                          const float* u_theta, const float* u_phi,
                          const float* u_g, const float* u_o) {
    __shared__ float sv[128];
    __shared__ float sred[128];
    const float* W; const float* u; float* Wn; int O, I;
    switch (blockIdx.x) {
        case 0:  W = w_theta; u = u_theta; Wn = g_Wt; O = CQ; I = CH; break;
        case 1:  W = w_phi;   u = u_phi;   Wn = g_Wp; O = CQ; I = CH; break;
        case 2:  W = w_g;     u = u_g;     Wn = g_Wg; O = CV; I = CH; break;
        default: W = w_o;     u = u_o;     Wn = g_Wo; O = CH; I = CV; break;
    }
    int t = threadIdx.x;
    float vr = 0.f;
    if (t < I) { for (int o = 0; o < O; o++) vr += u[o] * W[o * I + t]; }
    float nv2 = block_reduce_sum_128((t < I) ? vr * vr : 0.f, sred);
    float inv = 1.f / fmaxf(sqrtf(nv2), 1e-12f);
    if (t < I) sv[t] = vr * inv;
    __syncthreads();
    float ur = 0.f;
    if (t < O) { for (int i = 0; i < I; i++) ur += sv[i] * W[t * I + i]; }
    float nu2 = block_reduce_sum_128((t < O) ? ur * ur : 0.f, sred);
    float invu = 1.f / fmaxf(sqrtf(nu2), 1e-12f);
    float sigma = block_reduce_sum_128((t < O) ? ur * ur * invu : 0.f, sred);
    float wscale = 1.f / sigma;
    for (int k = t; k < O * I; k += 128) Wn[k] = W[k] * wscale;
}

// ---------------- fused input conv (theta | phi | g) via fp16 mma ----------------
#define XROW 272
#define SM_X 0
#define SM_W (128 * XROW)
#define CONV_SMEM (SM_W + 96 * XROW)

__global__ __launch_bounds__(256) void fusedconv_kernel(const float* __restrict__ x) {
    extern __shared__ char smc[];
    const u32 sXu = smem_u32(smc) + SM_X;
    const u32 sWu = smem_u32(smc) + SM_W;
    const int tid = threadIdx.x;
    const int w = tid >> 5, lane = tid & 31;
    const int b = blockIdx.x >> 5, j = blockIdx.x & 31;
    const int s0 = j * 128;

    for (int i = tid; i < 96 * 16; i += 256) {
        int out = i >> 4, seg = i & 15;
        const float* src;
        if (out < 16)      src = g_Wt + out * CH + seg * 8;
        else if (out < 32) src = g_Wp + (out - 16) * CH + seg * 8;
        else               src = g_Wg + (out - 32) * CH + seg * 8;
        float4 f0 = *(const float4*)src;
        float4 f1 = *(const float4*)(src + 4);
        uint4 v = make_uint4(h2u(f0.x, f0.y), h2u(f0.z, f0.w),
                             h2u(f1.x, f1.y), h2u(f1.z, f1.w));
        asm volatile("st.shared.v4.b32 [%0], {%1,%2,%3,%4};"
                     :: "r"(sWu + (u32)(out * XROW + seg * 16)),
                        "r"(v.x), "r"(v.y), "r"(v.z), "r"(v.w) : "memory");
    }
    for (int i = tid; i < 128 * 32; i += 256) {
        int ch = i >> 5, seg = i & 31;
        float4 f = *(const float4*)&x[((size_t)b * CH + ch) * HW + s0 + seg * 4];
        u32 h0 = h2u(f.x, f.y), h1 = h2u(f.z, f.w);
        asm volatile("st.shared.v2.b32 [%0], {%1,%2};"
                     :: "r"(sXu + (u32)(ch * XROW + seg * 8)), "r"(h0), "r"(h1) : "memory");
    }
    __syncthreads();

    const int jj = lane & 7, grp = lane >> 3;
    const u32 aBase = sXu + (u32)((((grp & 2) ? 8 : 0) + jj) * XROW
                                  + (16 * w + ((grp & 1) ? 8 : 0)) * 2);
    u32 bBase[6];
    #pragma unroll
    for (int np = 0; np < 6; np++)
        bBase[np] = sWu + (u32)((np * 16 + ((grp >> 1) ? 8 : 0) + jj) * XROW
                                + ((grp & 1) ? 16 : 0));

    float c[12][4];
    #pragma unroll
    for (int nt = 0; nt < 12; nt++)
        c[nt][0] = c[nt][1] = c[nt][2] = c[nt][3] = 0.f;

    #pragma unroll
    for (int t = 0; t < 8; t++) {
        u32 a[4];
        ldm4t(a[0], a[1], a[2], a[3], aBase + (u32)(t * 16 * XROW));
        #pragma unroll
        for (int np = 0; np < 6; np++) {
            u32 b0, b1, b2, b3;
            ldm4(b0, b1, b2, b3, bBase[np] + (u32)(t * 32));
            mmaf16(c[2 * np],     a, b0, b1);
            mmaf16(c[2 * np + 1], a, b2, b3);
        }
    }
    __syncthreads();

    const int g = lane >> 2, l = lane & 3;
    const int pxA = 16 * w + g;
    #pragma unroll
    for (int nt = 0; nt < 12; nt++) {
        u32 lo = h2u(c[nt][0], c[nt][1]);
        u32 hi = h2u(c[nt][2], c[nt][3]);
        asm volatile("st.shared.b32 [%0], %1;"
                     :: "r"(sXu + (u32)((pxA * 104 + nt * 8 + 2 * l) * 2)), "r"(lo) : "memory");
        asm volatile("st.shared.b32 [%0], %1;"
                     :: "r"(sXu + (u32)(((pxA + 8) * 104 + nt * 8 + 2 * l) * 2)), "r"(hi) : "memory");
    }
    __syncthreads();

    const __half* sCh = (const __half*)smc;
    {
        int px = tid >> 1, h = tid & 1;
        uint4 v = *(const uint4*)(sCh + px * 104 + h * 8);
        *(uint4*)&d_theta_h[((size_t)b * HW + s0 + px) * CQ + h * 8] = v;
    }
    if (tid < 64) {
        int wp = tid >> 1, h = tid & 1;
        int off = 16 + h * 8;
        const __half2* p0 = (const __half2*)(sCh + (2 * wp) * 104 + off);
        const __half2* p1 = (const __half2*)(sCh + (2 * wp + 1) * 104 + off);
        const __half2* p2 = (const __half2*)(sCh + (64 + 2 * wp) * 104 + off);
        const __half2* p3 = (const __half2*)(sCh + (65 + 2 * wp) * 104 + off);
        __half2 r[4];
        #pragma unroll
        for (int k = 0; k < 4; k++)
            r[k] = __hmax2(__hmax2(p0[k], p1[k]), __hmax2(p2[k], p3[k]));
        *(uint4*)&d_phi_h[((size_t)b * TT + j * 32 + wp) * CQ + h * 8] = *(uint4*)r;
    }
    if (tid < 128) {
        int ch = tid >> 1, wh = (tid & 1) * 16;
        __half2 outv[8];
        #pragma unroll
        for (int k2 = 0; k2 < 8; k2++) {
            __half v[2];
            #pragma unroll
            for (int u = 0; u < 2; u++) {
                int wp = wh + k2 * 2 + u;
                __half a0 = sCh[(2 * wp) * 104 + 32 + ch];
                __half a1 = sCh[(2 * wp + 1) * 104 + 32 + ch];
                __half a2 = sCh[(64 + 2 * wp) * 104 + 32 + ch];
                __half a3 = sCh[(65 + 2 * wp) * 104 + 32 + ch];
                v[u] = __hmax(__hmax(a0, a1), __hmax(a2, a3));
            }
            outv[k2] = __halves2half2(v[0], v[1]);
        }
        __half* dst = &d_gT_h[((size_t)b * CV + ch) * TT + j * 32 + wh];
        #pragma unroll
        for (int k2 = 0; k2 < 8; k2++) ((__half2*)dst)[k2] = outv[k2];
    }
}

// ---------------- attention: fp16 m16n8k16 flash, cp.async double-buffered ----
#define KSW 8
#define VSW 36
#define KSTG (64 * KSW)
#define VSTG (64 * VSW)
__global__ __launch_bounds__(256, 2) void attn_mma_kernel() {
    __shared__ u32 sK[2 * KSTG];
    __shared__ u32 sV[2 * VSTG];
    const int tid = threadIdx.x;
    const int w = tid >> 5, lane = tid & 31;
    const int g = lane >> 2, l = lane & 3;
    const int qbase = blockIdx.x * 128 + w * 16;
    const int b = (int)((blockIdx.x * 128) >> 12);
    const __half* phib = &d_phi_h[(size_t)(b << 10) * CQ];
    const __half* gTb  = &d_gT_h[(size_t)b * CV * TT];

    const u32 kbase = (u32)__cvta_generic_to_shared(sK);
    const u32 vbase = (u32)__cvta_generic_to_shared(sV);

    u32 qh[4];
    {
        const u32* q0 = (const u32*)&d_theta_h[(size_t)(qbase + g) * CQ];
        const u32* q1 = (const u32*)&d_theta_h[(size_t)(qbase + g + 8) * CQ];
        qh[0] = q0[l];     qh[1] = q1[l];
        qh[2] = q0[l + 4]; qh[3] = q1[l + 4];
    }

    float o[8][4];
    #pragma unroll
    for (int nt = 0; nt < 8; nt++)
        #pragma unroll
        for (int jj = 0; jj < 4; jj++) o[nt][jj] = 0.f;
    float mA = NEG_INF, mB = NEG_INF, lA = 0.f, lB = 0.f;

    auto fill = [&](int stage, int c0) {
        if (tid < 128) {
            int row = tid >> 1, part = tid & 1;
            cp16(kbase + (u32)((stage * KSTG + row * KSW + part * 4) * 4),
                 phib + (c0 + row) * CQ + part * 8);
        }
        #pragma unroll
        for (int i = 0; i < 2; i++) {
            int idx = tid * 2 + i;
            int c = idx >> 3, t8 = idx & 7;
            cp16(vbase + (u32)((stage * VSTG + c * VSW + t8 * 4) * 4),
                 gTb + (size_t)c * TT + c0 + t8 * 8);
        }
        cp_commit();
    };

    fill(0, 0);
    cp_wait0();
    __syncthreads();

    for (int c0 = 0; c0 < TT; c0 += 64) {
        int stage = (c0 >> 6) & 1;
        const u32* cK = sK + stage * KSTG;
        const u32* cV = sV + stage * VSTG;

        if (c0 + 64 < TT) fill(stage ^ 1, c0 + 64);

        float c[8][4];
        #pragma unroll
        for (int nt = 0; nt < 8; nt++) {
            c[nt][0] = c[nt][1] = c[nt][2] = c[nt][3] = 0.f;
            int kr = (nt * 8 + g) * KSW;
            mmaf16(c[nt], qh, cK[kr + l], cK[kr + l + 4]);
        }

        float cmA = NEG_INF, cmB = NEG_INF;
        #pragma unroll
        for (int nt = 0; nt < 8; nt++) {
            cmA = fmaxf(cmA, fmaxf(c[nt][0], c[nt][1]));
            cmB = fmaxf(cmB, fmaxf(c[nt][2], c[nt][3]));
        }
        cmA = fmaxf(cmA, __shfl_xor_sync(0xffffffffu, cmA, 1));
        cmA = fmaxf(cmA, __shfl_xor_sync(0xffffffffu, cmA, 2));
        cmB = fmaxf(cmB, __shfl_xor_sync(0xffffffffu, cmB, 1));
        cmB = fmaxf(cmB, __shfl_xor_sync(0xffffffffu, cmB, 2));
        float nmA = fmaxf(mA, cmA), nmB = fmaxf(mB, cmB);
        float sA = __expf(mA - nmA), sB = __expf(mB - nmB);
        mA = nmA; mB = nmB;
        lA *= sA; lB *= sB;

        u32 pa[4][4];
        #pragma unroll
        for (int nt = 0; nt < 8; nt++) {
            o[nt][0] *= sA; o[nt][1] *= sA; o[nt][2] *= sB; o[nt][3] *= sB;
            float p0 = __expf(c[nt][0] - mA);
            float p1 = __expf(c[nt][1] - mA);
            float p2 = __expf(c[nt][2] - mB);
            float p3 = __expf(c[nt][3] - mB);
            lA += p0 + p1; lB += p2 + p3;
            int kb = nt >> 1, hi = nt & 1;
            pa[kb][hi * 2]     = h2u(p0, p1);
            pa[kb][hi * 2 + 1] = h2u(p2, p3);
        }

        #pragma unroll
        for (int kb = 0; kb < 4; kb++) {
            #pragma unroll
            for (int nt = 0; nt < 8; nt++) {
                int vr = (nt * 8 + g) * VSW + kb * 8 + l;
                mmaf16(o[nt], pa[kb], cV[vr], cV[vr + 4]);
            }
        }

        cp_wait0();
        __syncthreads();
    }

    lA += __shfl_xor_sync(0xffffffffu, lA, 1);
    lA += __shfl_xor_sync(0xffffffffu, lA, 2);
    lB += __shfl_xor_sync(0xffffffffu, lB, 1);
    lB += __shfl_xor_sync(0xffffffffu, lB, 2);
    float iA = 1.f / lA, iB = 1.f / lB;
    #pragma unroll
    for (int nt = 0; nt < 8; nt++) {
        u32 r0 = h2u(o[nt][0] * iA, o[nt][1] * iA);
        u32 r1 = h2u(o[nt][2] * iB, o[nt][3] * iB);
        *(u32*)&d_o_h[(size_t)(qbase + g) * CV + nt * 8 + 2 * l] = r0;
        *(u32*)&d_o_h[(size_t)(qbase + g + 8) * CV + nt * 8 + 2 * l] = r1;
    }
}

// ---------------- output conv + residual via fp16 mma ----------------
// Block = (b, row-pair j): 128 px, 256 threads / 8 warps.
// A = o [128 px][64 k] fp16 (plain ldmatrix), B = Wo [128 out][64 k] fp16.
// Epilogue: two 64-channel halves bounced through smem [ch][132] f32, coalesced
// float4 writes of gamma*C + x.
#define OROWB 144                  // 72 halfs per row
#define OSM_W (128 * OROWB)        // 18432
#define OCONV_SMEM (OSM_W + 128 * OROWB)   // 36864

__global__ __launch_bounds__(256) void oconv_mma_kernel(const float* __restrict__ x,
                                                        const float* __restrict__ gptr,
                                                        float* __restrict__ out) {
    extern __shared__ char smc[];
    const u32 sOu = smem_u32(smc);
    const u32 sWu = sOu + OSM_W;
    float* sB = (float*)smc;       // bounce (reuses whole region after GEMM)
    const int tid = threadIdx.x;
    const int w = tid >> 5, lane = tid & 31;
    const int b = blockIdx.x >> 5, j = blockIdx.x & 31;
    const int s0 = j * 128;

    // fill W smem: Wo [128 out][64 k] f32 -> fp16, row stride 144B
    for (int i = tid; i < 128 * 8; i += 256) {
        int o8 = i >> 3, seg = i & 7;
        const float* src = g_Wo + o8 * CV + seg * 8;
        float4 f0 = *(const float4*)src;
        float4 f1 = *(const float4*)(src + 4);
        uint4 v = make_uint4(h2u(f0.x, f0.y), h2u(f0.z, f0.w),
                             h2u(f1.x, f1.y), h2u(f1.z, f1.w));
        asm volatile("st.shared.v4.b32 [%0], {%1,%2,%3,%4};"
                     :: "r"(sWu + (u32)(o8 * OROWB + seg * 16)),
                        "r"(v.x), "r"(v.y), "r"(v.z), "r"(v.w) : "memory");
    }
    // fill o smem: d_o_h [s0+px][64] fp16, row stride 144B
    for (int i = tid; i < 128 * 8; i += 256) {
        int px = i >> 3, seg = i & 7;
        cp16(sOu + (u32)(px * OROWB + seg * 16),
             d_o_h + ((size_t)b * HW + s0 + px) * CV + seg * 8);
    }
    cp_commit();
    cp_wait0();
    __syncthreads();

    const int jj = lane & 7, grp = lane >> 3;
    const u32 aBase = sOu + (u32)((16 * w + ((grp & 1) ? 8 : 0) + jj) * OROWB
                                  + ((grp & 2) ? 16 : 0));
    u32 bBase[8];
    #pragma unroll
    for (int np = 0; np < 8; np++)
        bBase[np] = sWu + (u32)((np * 16 + ((grp >> 1) ? 8 : 0) + jj) * OROWB
                                + ((grp & 1) ? 16 : 0));

    float c[16][4];
    #pragma unroll
    for (int nt = 0; nt < 16; nt++)
        c[nt][0] = c[nt][1] = c[nt][2] = c[nt][3] = 0.f;

    #pragma unroll
    for (int t = 0; t < 4; t++) {
        u32 a[4];
        ldm4(a[0], a[1], a[2], a[3], aBase + (u32)(t * 32));
        #pragma unroll
        for (int np = 0; np < 8; np++) {
            u32 b0, b1, b2, b3;
            ldm4(b0, b1, b2, b3, bBase[np] + (u32)(t * 32));
            mmaf16(c[2 * np],     a, b0, b1);
            mmaf16(c[2 * np + 1], a, b2, b3);
        }
    }
    __syncthreads();

    const float gamma = *gptr;
    const int g = lane >> 2, l = lane & 3;
    #pragma unroll
    for (int h = 0; h < 2; h++) {
        // fragments -> bounce smem [64 local ch][132] f32
        #pragma unroll
        for (int i = 0; i < 8; i++) {
            int nt = 8 * h + i;
            int cl = i * 8 + 2 * l;
            sB[cl * 132 + 16 * w + g]           = c[nt][0];
            sB[(cl + 1) * 132 + 16 * w + g]     = c[nt][1];
            sB[cl * 132 + 16 * w + g + 8]       = c[nt][2];
            sB[(cl + 1) * 132 + 16 * w + g + 8] = c[nt][3];
        }
        __syncthreads();
        // coalesced write: out = gamma*C + x
        #pragma unroll
        for (int k = 0; k < 8; k++) {
            int flat = k * 256 + tid;      // 2048 float4s = 64 ch x 32 groups
            int cc = flat >> 5, pxg = flat & 31;
            float4 v = *(const float4*)&sB[cc * 132 + pxg * 4];
            size_t idx = ((size_t)(b * CH) + 64 * h + cc) * HW + s0 + pxg * 4;
            float4 xv = *(const float4*)&x[idx];
            *(float4*)&out[idx] = make_float4(gamma * v.x + xv.x, gamma * v.y + xv.y,
                                              gamma * v.z + xv.z, gamma * v.w + xv.w);
        }
        __syncthreads();
    }
}

// ---------------- launch ----------------
extern "C" void kernel_launch(void* const* d_in, const int* in_sizes, int n_in,
                              void* d_out, int out_size) {
    const float* x       = (const float*)d_in[0];
    const float* w_theta = (const float*)d_in[1];
    const float* w_phi   = (const float*)d_in[2];
    const float* w_g     = (const float*)d_in[3];
    const float* w_o     = (const float*)d_in[4];
    const float* u_theta = (const float*)d_in[5];
    const float* u_phi   = (const float*)d_in[6];
    const float* u_g     = (const float*)d_in[7];
    const float* u_o     = (const float*)d_in[8];
    const float* gamma   = (const float*)d_in[9];
    float* out = (float*)d_out;

    cudaFuncSetAttribute(fusedconv_kernel, cudaFuncAttributeMaxDynamicSharedMemorySize, CONV_SMEM);
    cudaFuncSetAttribute(oconv_mma_kernel, cudaFuncAttributeMaxDynamicSharedMemorySize, OCONV_SMEM);

    sn_kernel<<<4, 128>>>(w_theta, w_phi, w_g, w_o, u_theta, u_phi, u_g, u_o);
    fusedconv_kernel<<<512, 256, CONV_SMEM>>>(x);
    attn_mma_kernel<<<512, 256>>>();
    oconv_mma_kernel<<<512, 256, OCONV_SMEM>>>(x, gamma, out);
}